// round 15
// baseline (speedup 1.0000x reference)
#include <cuda_runtime.h>
#include <cuda_fp16.h>
#include <cstdint>
#include <math.h>

#define B_   64
#define N_   197
#define C_   768
#define H_   12
#define HD_  64
#define BH_  (B_*H_)            // 768
#define MROWS (B_*N_)           // 12608
#define MASK_NEG_ -100000.0f
#define LOG2E_ 1.4426950408889634f

// ---------------- scratch ----------------
__device__ __align__(16) float  g_q[(size_t)BH_*N_*HD_];   // scaled q, [b,h,n,d]
__device__ __align__(16) float  g_k[(size_t)BH_*N_*HD_];
__device__ __align__(16) __half g_v[(size_t)BH_*N_*HD_];   // fp16 v (fused quantizes anyway)
__device__ __align__(16) __half g_ctx[(size_t)MROWS*C_];   // fp16 ctx
__device__ float g_mask[B_*N_];                            // additive mask

// ================= fp16 mma helpers =================
__device__ __forceinline__ void mma_f16(float acc[4], const uint32_t a[4], const uint32_t b[2]) {
    asm volatile("mma.sync.aligned.m16n8k16.row.col.f32.f16.f16.f32 "
        "{%0,%1,%2,%3}, {%4,%5,%6,%7}, {%8,%9}, {%0,%1,%2,%3};"
        : "+f"(acc[0]), "+f"(acc[1]), "+f"(acc[2]), "+f"(acc[3])
        : "r"(a[0]), "r"(a[1]), "r"(a[2]), "r"(a[3]), "r"(b[0]), "r"(b[1]));
}

__device__ __forceinline__ uint32_t pack_hi(float x, float y, float& lx, float& ly) {
    __half hx = __float2half_rn(x), hy = __float2half_rn(y);
    lx = x - __half2float(hx);
    ly = y - __half2float(hy);
    __half2 h = __halves2half2(hx, hy);
    return *reinterpret_cast<uint32_t*>(&h);
}
__device__ __forceinline__ uint32_t pack_lo(float lx, float ly) {
    __half2 h = __halves2half2(__float2half_rn(lx), __float2half_rn(ly));
    return *reinterpret_cast<uint32_t*>(&h);
}
__device__ __forceinline__ uint32_t pack_f16x2(float x, float y) {
    __half2 h = __floats2half2_rn(x, y);
    return *reinterpret_cast<uint32_t*>(&h);
}

__device__ __forceinline__ uint32_t ex2_f16x2(float t0, float t1) {
    __half2 h = __floats2half2_rn(t0, t1);
    uint32_t in = *reinterpret_cast<uint32_t*>(&h), out;
    asm("ex2.approx.f16x2 %0, %1;" : "=r"(out) : "r"(in));
    return out;
}

// ---- gemm smem layout: planes padded to 2112 words, kc bank-offset ----
#define PLANE_U32 2112
#define STAGE_U32 (4*PLANE_U32)
#define GEMM_SMEM_BYTES (128*4 + 2*STAGE_U32*4)   // 68096

#define A_IDX(kc, mt, lane, reg) (((((kc)*8  + (mt))*32 + (lane))*4 + (reg)) + (kc)*4)
#define B_IDX(kc, nt, lane, reg) (((((kc)*16 + (nt))*32 + (lane))*2 + (reg)) + (kc)*2)

// ================= fp16-split (Markidis) mma.sync GEMM =================
// 8 warps (2x4), warp tile 64x32, block tile 128x128, BK=32, double-buffered.
// MODE 0: A = x (fp32). q,k blocks (bn < 2C): 3-term. v blocks: 1-term.
// MODE 1: A = g_ctx (fp16): 1-term.
template<int MODE>
__global__ __launch_bounds__(256, 2)
void gemm_mma(const float* __restrict__ A_in, const float* __restrict__ W,
              const float* __restrict__ bias, float* __restrict__ out,
              int M, int N, int K)
{
    const float*  Af = A_in;
    const __half* Ah16 = g_ctx;
    extern __shared__ float sm[];
    float*    s_bias = sm;
    uint32_t* sbase  = reinterpret_cast<uint32_t*>(sm + 128);

    const int tid   = threadIdx.x;
    const int lane  = tid & 31;
    const int wid   = tid >> 5;
    const int warp_m = wid & 1;
    const int warp_n = wid >> 1;
    const int bm = blockIdx.y * 128, bn = blockIdx.x * 128;

    // one_term: MODE 1 (ctx fp16) or v blocks (x quantized to fp16, W fp16)
    const bool one_term = (MODE == 1) || (bn >= 2 * C_);

    if (tid < 128) s_bias[tid] = bias[bn + tid];

    float acc[4][4][4];
#pragma unroll
    for (int i = 0; i < 4; i++)
#pragma unroll
        for (int j = 0; j < 4; j++)
#pragma unroll
            for (int r = 0; r < 4; r++) acc[i][j][r] = 0.f;

    auto load_stage = [&](uint32_t* st, int k0) {
        uint32_t* dAh = st;
        uint32_t* dAl = st + PLANE_U32;
        uint32_t* dBh = st + 2*PLANE_U32;
        uint32_t* dBl = st + 3*PLANE_U32;
#pragma unroll
        for (int it = 0; it < 4; it++) {
            int linear = tid + it * 256;
            int row = linear >> 3;
            int c0  = (linear & 7) << 2;
            int kc  = c0 >> 4;
            int kin = c0 & 15;
            {
                int gm = bm + row;
                int mt = row >> 4, rr = row & 15, gr = rr & 7;
                int reg  = (rr >> 3) + ((kin >= 8) ? 2 : 0);
                int ln0  = gr * 4 + ((kin & 7) >> 1);
                if (MODE == 1) {
                    uint2 h2 = make_uint2(0u, 0u);
                    if (gm < M) h2 = *reinterpret_cast<const uint2*>(Ah16 + (size_t)gm * K + k0 + c0);
                    dAh[A_IDX(kc, mt, ln0,     reg)] = h2.x;
                    dAh[A_IDX(kc, mt, ln0 + 1, reg)] = h2.y;
                } else {
                    float4 v = make_float4(0.f, 0.f, 0.f, 0.f);
                    if (gm < M) v = *reinterpret_cast<const float4*>(Af + (size_t)gm * K + k0 + c0);
                    if (one_term) {
                        dAh[A_IDX(kc, mt, ln0,     reg)] = pack_f16x2(v.x, v.y);
                        dAh[A_IDX(kc, mt, ln0 + 1, reg)] = pack_f16x2(v.z, v.w);
                    } else {
                        float lx, ly, lz, lw;
                        uint32_t h01 = pack_hi(v.x, v.y, lx, ly);
                        uint32_t h23 = pack_hi(v.z, v.w, lz, lw);
                        dAh[A_IDX(kc, mt, ln0,     reg)] = h01;
                        dAh[A_IDX(kc, mt, ln0 + 1, reg)] = h23;
                        dAl[A_IDX(kc, mt, ln0,     reg)] = pack_lo(lx, ly);
                        dAl[A_IDX(kc, mt, ln0 + 1, reg)] = pack_lo(lz, lw);
                    }
                }
            }
            {
                float4 v = *reinterpret_cast<const float4*>(W + (size_t)(bn + row) * K + k0 + c0);
                int nt = row >> 3, nc = row & 7;
                int reg = (kin >= 8) ? 1 : 0;
                int ln0 = nc * 4 + ((kin & 7) >> 1);
                if (one_term) {
                    dBh[B_IDX(kc, nt, ln0,     reg)] = pack_f16x2(v.x, v.y);
                    dBh[B_IDX(kc, nt, ln0 + 1, reg)] = pack_f16x2(v.z, v.w);
                } else {
                    float lx, ly, lz, lw;
                    uint32_t h01 = pack_hi(v.x, v.y, lx, ly);
                    uint32_t h23 = pack_hi(v.z, v.w, lz, lw);
                    dBh[B_IDX(kc, nt, ln0,     reg)] = h01;
                    dBh[B_IDX(kc, nt, ln0 + 1, reg)] = h23;
                    dBl[B_IDX(kc, nt, ln0,     reg)] = pack_lo(lx, ly);
                    dBl[B_IDX(kc, nt, ln0 + 1, reg)] = pack_lo(lz, lw);
                }
            }
        }
    };

    auto compute_stage = [&](const uint32_t* st) {
        const uint32_t* cAh = st;
        const uint32_t* cAl = st + PLANE_U32;
        const uint32_t* cBh = st + 2*PLANE_U32;
        const uint32_t* cBl = st + 3*PLANE_U32;
#pragma unroll
        for (int kc = 0; kc < 2; kc++) {
            uint32_t ah[4][4], al[4][4];
#pragma unroll
            for (int im = 0; im < 4; im++) {
                int mt = warp_m * 4 + im;
                uint4 h = *reinterpret_cast<const uint4*>(&cAh[A_IDX(kc, mt, lane, 0)]);
                ah[im][0] = h.x; ah[im][1] = h.y; ah[im][2] = h.z; ah[im][3] = h.w;
                if (!one_term) {
                    uint4 l = *reinterpret_cast<const uint4*>(&cAl[A_IDX(kc, mt, lane, 0)]);
                    al[im][0] = l.x; al[im][1] = l.y; al[im][2] = l.z; al[im][3] = l.w;
                }
            }
#pragma unroll
            for (int jn = 0; jn < 4; jn++) {
                int nt = warp_n * 4 + jn;
                uint2 h = *reinterpret_cast<const uint2*>(&cBh[B_IDX(kc, nt, lane, 0)]);
                uint32_t bh[2] = { h.x, h.y };
                if (one_term) {
#pragma unroll
                    for (int im = 0; im < 4; im++)
                        mma_f16(acc[im][jn], ah[im], bh);
                } else {
                    uint2 l = *reinterpret_cast<const uint2*>(&cBl[B_IDX(kc, nt, lane, 0)]);
                    uint32_t bl[2] = { l.x, l.y };
#pragma unroll
                    for (int im = 0; im < 4; im++) {
                        mma_f16(acc[im][jn], al[im], bh);
                        mma_f16(acc[im][jn], ah[im], bl);
                        mma_f16(acc[im][jn], ah[im], bh);
                    }
                }
            }
        }
    };

    uint32_t* st0 = sbase;
    uint32_t* st1 = sbase + STAGE_U32;

    load_stage(st0, 0);
    __syncthreads();

    const int nchunk = K >> 5;
    for (int c = 0; c < nchunk; c++) {
        uint32_t* cur = (c & 1) ? st1 : st0;
        uint32_t* nxt = (c & 1) ? st0 : st1;
        if (c + 1 < nchunk) load_stage(nxt, (c + 1) << 5);
        compute_stage(cur);
        __syncthreads();
    }

#pragma unroll
    for (int im = 0; im < 4; im++) {
        int row0 = warp_m * 64 + im * 16 + (lane >> 2);
#pragma unroll
        for (int jn = 0; jn < 4; jn++) {
            int col0 = warp_n * 32 + jn * 8 + (lane & 3) * 2;
#pragma unroll
            for (int r = 0; r < 4; r++) {
                int m  = bm + row0 + ((r >= 2) ? 8 : 0);
                int cl = col0 + (r & 1);
                if (m >= M) continue;
                int cc = bn + cl;
                float val = acc[im][jn][r] + s_bias[cl];
                if (MODE == 0) {
                    int bb = m / N_;
                    int nn2 = m - bb * N_;
                    int part = cc / C_;
                    int rem  = cc - part * C_;
                    int h = rem >> 6;
                    int dd = rem & 63;
                    size_t idx = ((size_t)(bb * H_ + h) * N_ + nn2) * HD_ + dd;
                    if      (part == 0) g_q[idx] = val * 0.125f;
                    else if (part == 1) g_k[idx] = val;
                    else                g_v[idx] = __float2half_rn(val);
                } else {
                    out[(size_t)m * N + cc] = val;
                }
            }
        }
    }
}

// ================= cls scores + top-k -> g_mask, keep_mask =================
__global__ __launch_bounds__(256)
void cls_topk(float* __restrict__ keep_out, const int* __restrict__ num_keep)
{
    __shared__ float q0s[H_ * HD_];
    __shared__ float s[196];
    const int b = blockIdx.x;
    const int t = threadIdx.x;
    const int k = num_keep[0];

    for (int i = t; i < H_ * HD_; i += 256) {
        int h = i >> 6, d = i & 63;
        q0s[i] = g_q[((size_t)(b * H_ + h) * N_) * HD_ + d];
    }
    __syncthreads();

    if (t < 196) {
        float sum = 0.f;
#pragma unroll
        for (int h = 0; h < H_; h++) {
            const float* kr = g_k + ((size_t)(b * H_ + h) * N_ + (t + 1)) * HD_;
            const float* qr = q0s + h * HD_;
            float d0 = 0.f;
#pragma unroll
            for (int d = 0; d < HD_; d += 4) {
                float4 kv = *reinterpret_cast<const float4*>(kr + d);
                d0 += qr[d] * kv.x + qr[d+1] * kv.y + qr[d+2] * kv.z + qr[d+3] * kv.w;
            }
            sum += d0;
        }
        s[t] = sum * (1.0f / 12.0f);
    }
    __syncthreads();

    if (t < 196) {
        float mine = s[t];
        int rank = 0;
        for (int i = 0; i < 196; i++) {
            float si = s[i];
            rank += (si > mine) || (si == mine && i < t);
        }
        bool keep = rank < k;
        g_mask[b * N_ + t + 1]   = keep ? 0.f : MASK_NEG_;
        keep_out[b * N_ + t + 1] = keep ? 1.f : 0.f;
    }
    if (t == 0) {
        g_mask[b * N_]   = 0.f;
        keep_out[b * N_] = 1.f;
    }
}

// ================= fused: S = QK^T -> attn_rt, softmax, P@V -> ctx(fp16) =================
#define FQA_H 0
#define FQA_L 2048
#define FKB_H 4096
#define FVB_H 10752
#define FPA   4096
#define FMSK  17408
#define FRMAX 17616
#define FRSUM 17744
#define FUSED_SMEM_U32 17872
#define FUSED_SMEM_BYTES (FUSED_SMEM_U32*4)   // 71488

__global__ __launch_bounds__(256, 2)
void fused_attn(float* __restrict__ attn)
{
    extern __shared__ uint32_t smu[];
    float* msk  = reinterpret_cast<float*>(smu + FMSK);
    float* rmax = reinterpret_cast<float*>(smu + FRMAX);
    float* rsum = reinterpret_cast<float*>(smu + FRSUM);

    const int tid  = threadIdx.x;
    const int lane = tid & 31;
    const int wid  = tid >> 5;
    const int qt   = blockIdx.x;
    const int bh   = blockIdx.y;
    const int b    = bh / H_;
    const int h    = bh - b * H_;

    const float*  qb = g_q + (size_t)bh * N_ * HD_;
    const float*  kb = g_k + (size_t)bh * N_ * HD_;
    const __half* vb = g_v + (size_t)bh * N_ * HD_;

    if (tid < 208) msk[tid] = (tid < N_) ? g_mask[b * N_ + tid] : MASK_NEG_;

    // ---- Q loader (hi/lo) ----
#pragma unroll
    for (int it = 0; it < 4; it++) {
        int linear = tid + it * 256;
        int row = linear >> 4;
        int g = linear & 15;
        int kc = g >> 2, kin = (g & 3) << 2;
        int grow = qt * 64 + row;
        float4 v = make_float4(0.f, 0.f, 0.f, 0.f);
        if (grow < N_) v = *reinterpret_cast<const float4*>(qb + (size_t)grow * HD_ + kc * 16 + kin);
        int mt = row >> 4, rr = row & 15, gr = rr & 7;
        int reg = (rr >> 3) + ((kin >= 8) ? 2 : 0);
        int ln0 = gr * 4 + ((kin & 7) >> 1);
        float lx, ly, lz, lw;
        uint32_t h01 = pack_hi(v.x, v.y, lx, ly);
        uint32_t h23 = pack_hi(v.z, v.w, lz, lw);
        smu[FQA_H + ((kc*4 + mt)*32 + ln0    )*4 + reg] = h01;
        smu[FQA_H + ((kc*4 + mt)*32 + ln0 + 1)*4 + reg] = h23;
        smu[FQA_L + ((kc*4 + mt)*32 + ln0    )*4 + reg] = pack_lo(lx, ly);
        smu[FQA_L + ((kc*4 + mt)*32 + ln0 + 1)*4 + reg] = pack_lo(lz, lw);
    }
    // ---- K loader (hi only) ----
    for (int it = 0; it < 13; it++) {
        int linear = tid + it * 256;
        if (linear >= 3328) break;
        int row = linear >> 4;
        int g = linear & 15;
        int kc = g >> 2, kin = (g & 3) << 2;
        float4 v = make_float4(0.f, 0.f, 0.f, 0.f);
        if (row < N_) v = *reinterpret_cast<const float4*>(kb + (size_t)row * HD_ + kc * 16 + kin);
        int nt = row >> 3, nc = row & 7;
        int reg = (kin >= 8) ? 1 : 0;
        int ln0 = nc * 4 + ((kin & 7) >> 1);
        smu[FKB_H + ((kc*26 + nt)*32 + ln0    )*2 + reg] = pack_f16x2(v.x, v.y);
        smu[FKB_H + ((kc*26 + nt)*32 + ln0 + 1)*2 + reg] = pack_f16x2(v.z, v.w);
    }
    // ---- V loader (fp16 source, pure copy/transpose) ----
    for (int it = 0; it < 7; it++) {
        int task = tid + it * 256;
        if (task >= 1664) break;
        int dg = task & 15;
        int p  = task >> 4;
        int k0 = p * 2;
        // load 4 fp16 from each of two k rows
        uint2 r0 = make_uint2(0u, 0u), r1 = make_uint2(0u, 0u);
        if (k0 < N_)     r0 = *reinterpret_cast<const uint2*>(vb + (size_t)k0 * HD_ + dg * 4);
        if (k0 + 1 < N_) r1 = *reinterpret_cast<const uint2*>(vb + (size_t)(k0+1) * HD_ + dg * 4);
        const __half* h0 = reinterpret_cast<const __half*>(&r0);
        const __half* h1 = reinterpret_cast<const __half*>(&r1);
        int kc = k0 >> 4, kin = k0 & 15;
        int reg = (kin >= 8) ? 1 : 0;
        int lbits = (kin >> 1) & 3;
#pragma unroll
        for (int j = 0; j < 4; j++) {
            int d = dg * 4 + j;
            int nt = d >> 3, nl = d & 7;
            int ln = (nl << 2) | lbits;
            __half2 pr = __halves2half2(h0[j], h1[j]);
            smu[FVB_H + ((kc*8 + nt)*32 + ln)*2 + reg] = *reinterpret_cast<uint32_t*>(&pr);
        }
    }
    __syncthreads();

    const int m    = wid & 3;
    const int half = wid >> 2;
    const int nt0  = half * 13;
    const bool mvalid = (qt * 64 + m * 16) < N_;

    float acc[13][4];
    uint32_t pa0[13], pa1[13];

    if (mvalid) {
#pragma unroll
        for (int i = 0; i < 13; i++)
#pragma unroll
            for (int r = 0; r < 4; r++) acc[i][r] = 0.f;

#pragma unroll
        for (int kc = 0; kc < 4; kc++) {
            uint4 h4 = *reinterpret_cast<const uint4*>(&smu[FQA_H + ((kc*4 + m)*32 + lane)*4]);
            uint4 l4 = *reinterpret_cast<const uint4*>(&smu[FQA_L + ((kc*4 + m)*32 + lane)*4]);
            uint32_t ah[4] = { h4.x, h4.y, h4.z, h4.w };
            uint32_t al[4] = { l4.x, l4.y, l4.z, l4.w };
#pragma unroll
            for (int i = 0; i < 13; i++) {
                int nt = nt0 + i;
                uint2 bh2 = *reinterpret_cast<const uint2*>(&smu[FKB_H + ((kc*26 + nt)*32 + lane)*2]);
                uint32_t bhv[2] = { bh2.x, bh2.y };
                mma_f16(acc[i], al, bhv);
                mma_f16(acc[i], ah, bhv);
            }
        }

        {
            float* ab = attn + (size_t)bh * N_ * N_;
            int r0 = qt * 64 + m * 16 + (lane >> 2);
            int cb = (lane & 3) * 2;
#pragma unroll
            for (int i = 0; i < 13; i++) {
                int col0 = (nt0 + i) * 8 + cb;
                if (r0 < N_) {
                    if (col0 < N_)     ab[(size_t)r0 * N_ + col0]     = acc[i][0];
                    if (col0 + 1 < N_) ab[(size_t)r0 * N_ + col0 + 1] = acc[i][1];
                }
                if (r0 + 8 < N_) {
                    if (col0 < N_)     ab[(size_t)(r0+8) * N_ + col0]     = acc[i][2];
                    if (col0 + 1 < N_) ab[(size_t)(r0+8) * N_ + col0 + 1] = acc[i][3];
                }
            }
        }

        float mx0 = -1e30f, mx1 = -1e30f;
#pragma unroll
        for (int i = 0; i < 13; i++) {
            int col0 = (nt0 + i) * 8 + (lane & 3) * 2;
            float2 mk = *reinterpret_cast<const float2*>(&msk[col0]);
            acc[i][0] += mk.x; acc[i][1] += mk.y;
            acc[i][2] += mk.x; acc[i][3] += mk.y;
            mx0 = fmaxf(mx0, fmaxf(acc[i][0], acc[i][1]));
            mx1 = fmaxf(mx1, fmaxf(acc[i][2], acc[i][3]));
        }
#pragma unroll
        for (int o = 1; o < 4; o <<= 1) {
            mx0 = fmaxf(mx0, __shfl_xor_sync(0xffffffffu, mx0, o));
            mx1 = fmaxf(mx1, __shfl_xor_sync(0xffffffffu, mx1, o));
        }
        if ((lane & 3) == 0) {
            rmax[half * 64 + m * 16 + (lane >> 2)]     = mx0;
            rmax[half * 64 + m * 16 + (lane >> 2) + 8] = mx1;
        }
    }
    __syncthreads();

    if (mvalid) {
        float mx0, mx1;
        {
            int rl = m * 16 + (lane >> 2);
            mx0 = fmaxf(rmax[rl], rmax[64 + rl]);
            mx1 = fmaxf(rmax[rl + 8], rmax[64 + rl + 8]);
        }
        float sum0 = 0.f, sum1 = 0.f;
#pragma unroll
        for (int i = 0; i < 13; i++) {
            pa0[i] = ex2_f16x2((acc[i][0] - mx0) * LOG2E_, (acc[i][1] - mx0) * LOG2E_);
            pa1[i] = ex2_f16x2((acc[i][2] - mx1) * LOG2E_, (acc[i][3] - mx1) * LOG2E_);
            float2 f0 = __half22float2(*reinterpret_cast<__half2*>(&pa0[i]));
            float2 f1 = __half22float2(*reinterpret_cast<__half2*>(&pa1[i]));
            sum0 += f0.x + f0.y;
            sum1 += f1.x + f1.y;
        }
#pragma unroll
        for (int o = 1; o < 4; o <<= 1) {
            sum0 += __shfl_xor_sync(0xffffffffu, sum0, o);
            sum1 += __shfl_xor_sync(0xffffffffu, sum1, o);
        }
        if ((lane & 3) == 0) {
            rsum[half * 64 + m * 16 + (lane >> 2)]     = sum0;
            rsum[half * 64 + m * 16 + (lane >> 2) + 8] = sum1;
        }
    }
    __syncthreads();

    if (mvalid) {
#pragma unroll
        for (int i = 0; i < 13; i++) {
            int nt = nt0 + i;
            int kcp = nt >> 1;
            int odd = nt & 1;
            int base = FPA + ((kcp*4 + m)*32 + lane)*4 + odd*2;
            smu[base]     = pa0[i];
            smu[base + 1] = pa1[i];
        }
    }
    __syncthreads();

    // ---- phase 2: ctx = P @ V (V single fp16), store fp16 ----
    const int mo = wid & 3;
    const int nq = wid >> 2;
    const bool movalid = (qt * 64 + mo * 16) < N_;

    if (movalid) {
        float acc2[4][4];
#pragma unroll
        for (int o = 0; o < 4; o++)
#pragma unroll
            for (int r = 0; r < 4; r++) acc2[o][r] = 0.f;

#pragma unroll
        for (int kcp = 0; kcp < 13; kcp++) {
            uint4 a4 = *reinterpret_cast<const uint4*>(&smu[FPA + ((kcp*4 + mo)*32 + lane)*4]);
            uint32_t av[4] = { a4.x, a4.y, a4.z, a4.w };
#pragma unroll
            for (int o = 0; o < 4; o++) {
                int ont = nq * 4 + o;
                uint2 bh2 = *reinterpret_cast<const uint2*>(&smu[FVB_H + ((kcp*8 + ont)*32 + lane)*2]);
                uint32_t bhv[2] = { bh2.x, bh2.y };
                mma_f16(acc2[o], av, bhv);
            }
        }

        int rl0 = mo * 16 + (lane >> 2);
        int row0 = qt * 64 + rl0;
        float inv0 = 1.f / (rsum[rl0] + rsum[64 + rl0]);
        float inv1 = 1.f / (rsum[rl0 + 8] + rsum[64 + rl0 + 8]);
#pragma unroll
        for (int o = 0; o < 4; o++) {
            int col0 = (nq * 4 + o) * 8 + (lane & 3) * 2;
            if (row0 < N_) {
                size_t off = ((size_t)(b * N_ + row0) * H_ + h) * HD_ + col0;
                __half2 hc = __floats2half2_rn(acc2[o][0] * inv0, acc2[o][1] * inv0);
                *reinterpret_cast<__half2*>(g_ctx + off) = hc;
            }
            if (row0 + 8 < N_) {
                size_t off = ((size_t)(b * N_ + row0 + 8) * H_ + h) * HD_ + col0;
                __half2 hc = __floats2half2_rn(acc2[o][2] * inv1, acc2[o][3] * inv1);
                *reinterpret_cast<__half2*>(g_ctx + off) = hc;
            }
        }
    }
}

// ---------------- launch ----------------
extern "C" void kernel_launch(void* const* d_in, const int* in_sizes, int n_in,
                              void* d_out, int out_size)
{
    const float* x      = (const float*)d_in[0];
    const float* qkv_w  = (const float*)d_in[1];
    const float* qkv_b  = (const float*)d_in[2];
    const float* proj_w = (const float*)d_in[3];
    const float* proj_b = (const float*)d_in[4];
    const int*   nkeep  = (const int*)  d_in[5];

    float* out       = (float*)d_out;                       // [B,N,C]
    float* keep_mask = out + (size_t)MROWS * C_;            // [B,N,1]
    float* attn      = keep_mask + MROWS;                   // [B,H,N,N]

    cudaFuncSetAttribute((const void*)gemm_mma<0>,
                         cudaFuncAttributeMaxDynamicSharedMemorySize, GEMM_SMEM_BYTES);
    cudaFuncSetAttribute((const void*)gemm_mma<1>,
                         cudaFuncAttributeMaxDynamicSharedMemorySize, GEMM_SMEM_BYTES);
    cudaFuncSetAttribute((const void*)fused_attn,
                         cudaFuncAttributeMaxDynamicSharedMemorySize, FUSED_SMEM_BYTES);

    // 1) qkv GEMM -> g_q (scaled), g_k, g_v(fp16)  (v blocks 1-term)
    gemm_mma<0><<<dim3((3 * C_) / 128, (MROWS + 127) / 128), 256, GEMM_SMEM_BYTES>>>(
        x, qkv_w, qkv_b, nullptr, MROWS, 3 * C_, C_);

    // 2) cls scores + top-k -> g_mask, keep_mask (fp32, independent of fused S)
    cls_topk<<<B_, 256>>>(keep_mask, nkeep);

    // 3) fused scores + attn_rt write + softmax + AV -> g_ctx (fp16)
    fused_attn<<<dim3(4, BH_), 256, FUSED_SMEM_BYTES>>>(attn);

    // 4) proj GEMM -> out  (A fp16, 1-term)
    gemm_mma<1><<<dim3(C_ / 128, (MROWS + 127) / 128), 256, GEMM_SMEM_BYTES>>>(
        nullptr, proj_w, proj_b, out, MROWS, C_, C_);
}

// round 16
// speedup vs baseline: 1.1399x; 1.1399x over previous
#include <cuda_runtime.h>
#include <cuda_fp16.h>
#include <cstdint>
#include <math.h>

#define B_   64
#define N_   197
#define C_   768
#define H_   12
#define HD_  64
#define BH_  (B_*H_)            // 768
#define MROWS (B_*N_)           // 12608
#define MASK_NEG_ -100000.0f
#define LOG2E_ 1.4426950408889634f

// ---------------- scratch ----------------
__device__ __align__(16) float  g_q[(size_t)BH_*N_*HD_];   // scaled q, [b,h,n,d]
__device__ __align__(16) float  g_k[(size_t)BH_*N_*HD_];
__device__ __align__(16) float  g_v[(size_t)BH_*N_*HD_];
__device__ __align__(16) __half g_ctx[(size_t)MROWS*C_];   // fp16 ctx
__device__ __align__(16) __half g_pw16[(size_t)C_*C_];     // fp16 proj_w
__device__ float g_mask[B_*N_];                            // additive mask

// ================= fp16 mma helpers =================
__device__ __forceinline__ void mma_f16(float acc[4], const uint32_t a[4], const uint32_t b[2]) {
    asm volatile("mma.sync.aligned.m16n8k16.row.col.f32.f16.f16.f32 "
        "{%0,%1,%2,%3}, {%4,%5,%6,%7}, {%8,%9}, {%0,%1,%2,%3};"
        : "+f"(acc[0]), "+f"(acc[1]), "+f"(acc[2]), "+f"(acc[3])
        : "r"(a[0]), "r"(a[1]), "r"(a[2]), "r"(a[3]), "r"(b[0]), "r"(b[1]));
}

__device__ __forceinline__ uint32_t pack_hi(float x, float y, float& lx, float& ly) {
    __half hx = __float2half_rn(x), hy = __float2half_rn(y);
    lx = x - __half2float(hx);
    ly = y - __half2float(hy);
    __half2 h = __halves2half2(hx, hy);
    return *reinterpret_cast<uint32_t*>(&h);
}
__device__ __forceinline__ uint32_t pack_lo(float lx, float ly) {
    __half2 h = __halves2half2(__float2half_rn(lx), __float2half_rn(ly));
    return *reinterpret_cast<uint32_t*>(&h);
}
__device__ __forceinline__ uint32_t pack_f16x2(float x, float y) {
    __half2 h = __floats2half2_rn(x, y);
    return *reinterpret_cast<uint32_t*>(&h);
}

__device__ __forceinline__ uint32_t ex2_f16x2(float t0, float t1) {
    __half2 h = __floats2half2_rn(t0, t1);
    uint32_t in = *reinterpret_cast<uint32_t*>(&h), out;
    asm("ex2.approx.f16x2 %0, %1;" : "=r"(out) : "r"(in));
    return out;
}

// ================= proj_w fp32 -> fp16 (one-time, rn: identical to loader cvt) =================
__global__ __launch_bounds__(256)
void conv_w16(const float* __restrict__ w, int n4)
{
    int i = blockIdx.x * blockDim.x + threadIdx.x;
    if (i >= n4) return;
    float4 v = reinterpret_cast<const float4*>(w)[i];
    __half2 h0 = __floats2half2_rn(v.x, v.y);
    __half2 h1 = __floats2half2_rn(v.z, v.w);
    reinterpret_cast<__half2*>(g_pw16)[2*i]   = h0;
    reinterpret_cast<__half2*>(g_pw16)[2*i+1] = h1;
}

// ---- gemm smem layout: planes padded to 2112 words, kc bank-offset ----
#define PLANE_U32 2112
#define STAGE_U32 (4*PLANE_U32)
#define GEMM_SMEM_BYTES (128*4 + 2*STAGE_U32*4)   // 68096

#define A_IDX(kc, mt, lane, reg) (((((kc)*8  + (mt))*32 + (lane))*4 + (reg)) + (kc)*4)
#define B_IDX(kc, nt, lane, reg) (((((kc)*16 + (nt))*32 + (lane))*2 + (reg)) + (kc)*2)

// ================= fp16-split (Markidis) mma.sync GEMM =================
// 8 warps (2x4), warp tile 64x32, block tile 128x128, BK=32, double-buffered.
// MODE 0: A = x (fp32). q,k blocks: 3-term. v blocks (bn >= 2C): 2-term.
// MODE 1: A = g_ctx (fp16), B = g_pw16 (fp16) -> 1-term, pure-copy loader.
template<int MODE>
__global__ __launch_bounds__(256, 2)
void gemm_mma(const float* __restrict__ A_in, const float* __restrict__ W,
              const float* __restrict__ bias, float* __restrict__ out,
              int M, int N, int K)
{
    const float*  Af = A_in;
    const __half* Ah16 = g_ctx;
    const __half* Wh16 = g_pw16;
    extern __shared__ float sm[];
    float*    s_bias = sm;
    uint32_t* sbase  = reinterpret_cast<uint32_t*>(sm + 128);

    const int tid   = threadIdx.x;
    const int lane  = tid & 31;
    const int wid   = tid >> 5;
    const int warp_m = wid & 1;
    const int warp_n = wid >> 1;
    const int bm = blockIdx.y * 128, bn = blockIdx.x * 128;

    const bool tt = (MODE == 1) || (bn >= 2 * C_);

    if (tid < 128) s_bias[tid] = bias[bn + tid];

    float acc[4][4][4];
#pragma unroll
    for (int i = 0; i < 4; i++)
#pragma unroll
        for (int j = 0; j < 4; j++)
#pragma unroll
            for (int r = 0; r < 4; r++) acc[i][j][r] = 0.f;

    auto load_stage = [&](uint32_t* st, int k0) {
        uint32_t* dAh = st;
        uint32_t* dAl = st + PLANE_U32;
        uint32_t* dBh = st + 2*PLANE_U32;
        uint32_t* dBl = st + 3*PLANE_U32;
#pragma unroll
        for (int it = 0; it < 4; it++) {
            int linear = tid + it * 256;
            int row = linear >> 3;
            int c0  = (linear & 7) << 2;
            int kc  = c0 >> 4;
            int kin = c0 & 15;
            {
                int gm = bm + row;
                int mt = row >> 4, rr = row & 15, gr = rr & 7;
                int reg  = (rr >> 3) + ((kin >= 8) ? 2 : 0);
                int ln0  = gr * 4 + ((kin & 7) >> 1);
                if (MODE == 1) {
                    uint2 h2 = make_uint2(0u, 0u);
                    if (gm < M) h2 = *reinterpret_cast<const uint2*>(Ah16 + (size_t)gm * K + k0 + c0);
                    dAh[A_IDX(kc, mt, ln0,     reg)] = h2.x;
                    dAh[A_IDX(kc, mt, ln0 + 1, reg)] = h2.y;
                } else {
                    float4 v = make_float4(0.f, 0.f, 0.f, 0.f);
                    if (gm < M) v = *reinterpret_cast<const float4*>(Af + (size_t)gm * K + k0 + c0);
                    float lx, ly, lz, lw;
                    uint32_t h01 = pack_hi(v.x, v.y, lx, ly);
                    uint32_t h23 = pack_hi(v.z, v.w, lz, lw);
                    dAh[A_IDX(kc, mt, ln0,     reg)] = h01;
                    dAh[A_IDX(kc, mt, ln0 + 1, reg)] = h23;
                    dAl[A_IDX(kc, mt, ln0,     reg)] = pack_lo(lx, ly);
                    dAl[A_IDX(kc, mt, ln0 + 1, reg)] = pack_lo(lz, lw);
                }
            }
            {
                int nt = row >> 3, nc = row & 7;
                int reg = (kin >= 8) ? 1 : 0;
                int ln0 = nc * 4 + ((kin & 7) >> 1);
                if (MODE == 1) {
                    uint2 h2 = *reinterpret_cast<const uint2*>(Wh16 + (size_t)(bn + row) * K + k0 + c0);
                    dBh[B_IDX(kc, nt, ln0,     reg)] = h2.x;
                    dBh[B_IDX(kc, nt, ln0 + 1, reg)] = h2.y;
                } else {
                    float4 v = *reinterpret_cast<const float4*>(W + (size_t)(bn + row) * K + k0 + c0);
                    float lx, ly, lz, lw;
                    uint32_t h01 = pack_hi(v.x, v.y, lx, ly);
                    uint32_t h23 = pack_hi(v.z, v.w, lz, lw);
                    dBh[B_IDX(kc, nt, ln0,     reg)] = h01;
                    dBh[B_IDX(kc, nt, ln0 + 1, reg)] = h23;
                    if (!tt) {
                        dBl[B_IDX(kc, nt, ln0,     reg)] = pack_lo(lx, ly);
                        dBl[B_IDX(kc, nt, ln0 + 1, reg)] = pack_lo(lz, lw);
                    }
                }
            }
        }
    };

    auto compute_stage = [&](const uint32_t* st) {
        const uint32_t* cAh = st;
        const uint32_t* cAl = st + PLANE_U32;
        const uint32_t* cBh = st + 2*PLANE_U32;
        const uint32_t* cBl = st + 3*PLANE_U32;
#pragma unroll
        for (int kc = 0; kc < 2; kc++) {
            uint32_t ah[4][4], al[4][4];
#pragma unroll
            for (int im = 0; im < 4; im++) {
                int mt = warp_m * 4 + im;
                uint4 h = *reinterpret_cast<const uint4*>(&cAh[A_IDX(kc, mt, lane, 0)]);
                ah[im][0] = h.x; ah[im][1] = h.y; ah[im][2] = h.z; ah[im][3] = h.w;
                if (MODE == 0) {
                    uint4 l = *reinterpret_cast<const uint4*>(&cAl[A_IDX(kc, mt, lane, 0)]);
                    al[im][0] = l.x; al[im][1] = l.y; al[im][2] = l.z; al[im][3] = l.w;
                }
            }
#pragma unroll
            for (int jn = 0; jn < 4; jn++) {
                int nt = warp_n * 4 + jn;
                uint2 h = *reinterpret_cast<const uint2*>(&cBh[B_IDX(kc, nt, lane, 0)]);
                uint32_t bh[2] = { h.x, h.y };
                if (MODE == 1) {
#pragma unroll
                    for (int im = 0; im < 4; im++)
                        mma_f16(acc[im][jn], ah[im], bh);
                } else if (tt) {
#pragma unroll
                    for (int im = 0; im < 4; im++) {
                        mma_f16(acc[im][jn], al[im], bh);
                        mma_f16(acc[im][jn], ah[im], bh);
                    }
                } else {
                    uint2 l = *reinterpret_cast<const uint2*>(&cBl[B_IDX(kc, nt, lane, 0)]);
                    uint32_t bl[2] = { l.x, l.y };
#pragma unroll
                    for (int im = 0; im < 4; im++) {
                        mma_f16(acc[im][jn], al[im], bh);
                        mma_f16(acc[im][jn], ah[im], bl);
                        mma_f16(acc[im][jn], ah[im], bh);
                    }
                }
            }
        }
    };

    uint32_t* st0 = sbase;
    uint32_t* st1 = sbase + STAGE_U32;

    load_stage(st0, 0);
    __syncthreads();

    const int nchunk = K >> 5;
    for (int c = 0; c < nchunk; c++) {
        uint32_t* cur = (c & 1) ? st1 : st0;
        uint32_t* nxt = (c & 1) ? st0 : st1;
        if (c + 1 < nchunk) load_stage(nxt, (c + 1) << 5);
        compute_stage(cur);
        __syncthreads();
    }

#pragma unroll
    for (int im = 0; im < 4; im++) {
        int row0 = warp_m * 64 + im * 16 + (lane >> 2);
#pragma unroll
        for (int jn = 0; jn < 4; jn++) {
            int col0 = warp_n * 32 + jn * 8 + (lane & 3) * 2;
#pragma unroll
            for (int r = 0; r < 4; r++) {
                int m  = bm + row0 + ((r >= 2) ? 8 : 0);
                int cl = col0 + (r & 1);
                if (m >= M) continue;
                int cc = bn + cl;
                float val = acc[im][jn][r] + s_bias[cl];
                if (MODE == 0) {
                    int bb = m / N_;
                    int nn2 = m - bb * N_;
                    int part = cc / C_;
                    int rem  = cc - part * C_;
                    int h = rem >> 6;
                    int dd = rem & 63;
                    size_t idx = ((size_t)(bb * H_ + h) * N_ + nn2) * HD_ + dd;
                    if      (part == 0) g_q[idx] = val * 0.125f;
                    else if (part == 1) g_k[idx] = val;
                    else                g_v[idx] = val;
                } else {
                    out[(size_t)m * N + cc] = val;
                }
            }
        }
    }
}

// ================= cls scores + top-k -> g_mask, keep_mask =================
__global__ __launch_bounds__(256)
void cls_topk(float* __restrict__ keep_out, const int* __restrict__ num_keep)
{
    __shared__ float q0s[H_ * HD_];
    __shared__ float s[196];
    const int b = blockIdx.x;
    const int t = threadIdx.x;
    const int k = num_keep[0];

    for (int i = t; i < H_ * HD_; i += 256) {
        int h = i >> 6, d = i & 63;
        q0s[i] = g_q[((size_t)(b * H_ + h) * N_) * HD_ + d];
    }
    __syncthreads();

    if (t < 196) {
        float sum = 0.f;
#pragma unroll
        for (int h = 0; h < H_; h++) {
            const float* kr = g_k + ((size_t)(b * H_ + h) * N_ + (t + 1)) * HD_;
            const float* qr = q0s + h * HD_;
            float d0 = 0.f;
#pragma unroll
            for (int d = 0; d < HD_; d += 4) {
                float4 kv = *reinterpret_cast<const float4*>(kr + d);
                d0 += qr[d] * kv.x + qr[d+1] * kv.y + qr[d+2] * kv.z + qr[d+3] * kv.w;
            }
            sum += d0;
        }
        s[t] = sum * (1.0f / 12.0f);
    }
    __syncthreads();

    if (t < 196) {
        float mine = s[t];
        int rank = 0;
        for (int i = 0; i < 196; i++) {
            float si = s[i];
            rank += (si > mine) || (si == mine && i < t);
        }
        bool keep = rank < k;
        g_mask[b * N_ + t + 1]   = keep ? 0.f : MASK_NEG_;
        keep_out[b * N_ + t + 1] = keep ? 1.f : 0.f;
    }
    if (t == 0) {
        g_mask[b * N_]   = 0.f;
        keep_out[b * N_] = 1.f;
    }
}

// ================= fused: S = QK^T -> attn_rt, softmax, P@V -> ctx(fp16) =================
#define FQA_H 0
#define FQA_L 2048
#define FKB_H 4096
#define FVB_H 10752
#define FPA   4096
#define FMSK  17408
#define FRMAX 17616
#define FRSUM 17744
#define FUSED_SMEM_U32 17872
#define FUSED_SMEM_BYTES (FUSED_SMEM_U32*4)   // 71488

__global__ __launch_bounds__(256, 2)
void fused_attn(float* __restrict__ attn)
{
    extern __shared__ uint32_t smu[];
    float* msk  = reinterpret_cast<float*>(smu + FMSK);
    float* rmax = reinterpret_cast<float*>(smu + FRMAX);
    float* rsum = reinterpret_cast<float*>(smu + FRSUM);

    const int tid  = threadIdx.x;
    const int lane = tid & 31;
    const int wid  = tid >> 5;
    const int qt   = blockIdx.x;
    const int bh   = blockIdx.y;
    const int b    = bh / H_;
    const int h    = bh - b * H_;

    const float* qb = g_q + (size_t)bh * N_ * HD_;
    const float* kb = g_k + (size_t)bh * N_ * HD_;
    const float* vb = g_v + (size_t)bh * N_ * HD_;

    if (tid < 208) msk[tid] = (tid < N_) ? g_mask[b * N_ + tid] : MASK_NEG_;

    // ---- Q loader (hi/lo) ----
#pragma unroll
    for (int it = 0; it < 4; it++) {
        int linear = tid + it * 256;
        int row = linear >> 4;
        int g = linear & 15;
        int kc = g >> 2, kin = (g & 3) << 2;
        int grow = qt * 64 + row;
        float4 v = make_float4(0.f, 0.f, 0.f, 0.f);
        if (grow < N_) v = *reinterpret_cast<const float4*>(qb + (size_t)grow * HD_ + kc * 16 + kin);
        int mt = row >> 4, rr = row & 15, gr = rr & 7;
        int reg = (rr >> 3) + ((kin >= 8) ? 2 : 0);
        int ln0 = gr * 4 + ((kin & 7) >> 1);
        float lx, ly, lz, lw;
        uint32_t h01 = pack_hi(v.x, v.y, lx, ly);
        uint32_t h23 = pack_hi(v.z, v.w, lz, lw);
        smu[FQA_H + ((kc*4 + mt)*32 + ln0    )*4 + reg] = h01;
        smu[FQA_H + ((kc*4 + mt)*32 + ln0 + 1)*4 + reg] = h23;
        smu[FQA_L + ((kc*4 + mt)*32 + ln0    )*4 + reg] = pack_lo(lx, ly);
        smu[FQA_L + ((kc*4 + mt)*32 + ln0 + 1)*4 + reg] = pack_lo(lz, lw);
    }
    // ---- K loader (hi only) ----
    for (int it = 0; it < 13; it++) {
        int linear = tid + it * 256;
        if (linear >= 3328) break;
        int row = linear >> 4;
        int g = linear & 15;
        int kc = g >> 2, kin = (g & 3) << 2;
        float4 v = make_float4(0.f, 0.f, 0.f, 0.f);
        if (row < N_) v = *reinterpret_cast<const float4*>(kb + (size_t)row * HD_ + kc * 16 + kin);
        int nt = row >> 3, nc = row & 7;
        int reg = (kin >= 8) ? 1 : 0;
        int ln0 = nc * 4 + ((kin & 7) >> 1);
        smu[FKB_H + ((kc*26 + nt)*32 + ln0    )*2 + reg] = pack_f16x2(v.x, v.y);
        smu[FKB_H + ((kc*26 + nt)*32 + ln0 + 1)*2 + reg] = pack_f16x2(v.z, v.w);
    }
    // ---- V loader (hi only) ----
    for (int it = 0; it < 7; it++) {
        int task = tid + it * 256;
        if (task >= 1664) break;
        int dg = task & 15;
        int p  = task >> 4;
        int k0 = p * 2;
        float4 v0 = make_float4(0.f,0.f,0.f,0.f), v1 = make_float4(0.f,0.f,0.f,0.f);
        if (k0 < N_)     v0 = *reinterpret_cast<const float4*>(vb + (size_t)k0 * HD_ + dg * 4);
        if (k0 + 1 < N_) v1 = *reinterpret_cast<const float4*>(vb + (size_t)(k0+1) * HD_ + dg * 4);
        int kc = k0 >> 4, kin = k0 & 15;
        int reg = (kin >= 8) ? 1 : 0;
        int lbits = (kin >> 1) & 3;
        const float* a0 = &v0.x;
        const float* a1 = &v1.x;
#pragma unroll
        for (int j = 0; j < 4; j++) {
            int d = dg * 4 + j;
            int nt = d >> 3, nl = d & 7;
            int ln = (nl << 2) | lbits;
            smu[FVB_H + ((kc*8 + nt)*32 + ln)*2 + reg] = pack_f16x2(a0[j], a1[j]);
        }
    }
    __syncthreads();

    const int m    = wid & 3;
    const int half = wid >> 2;
    const int nt0  = half * 13;
    const bool mvalid = (qt * 64 + m * 16) < N_;

    float acc[13][4];
    uint32_t pa0[13], pa1[13];

    if (mvalid) {
#pragma unroll
        for (int i = 0; i < 13; i++)
#pragma unroll
            for (int r = 0; r < 4; r++) acc[i][r] = 0.f;

#pragma unroll
        for (int kc = 0; kc < 4; kc++) {
            uint4 h4 = *reinterpret_cast<const uint4*>(&smu[FQA_H + ((kc*4 + m)*32 + lane)*4]);
            uint4 l4 = *reinterpret_cast<const uint4*>(&smu[FQA_L + ((kc*4 + m)*32 + lane)*4]);
            uint32_t ah[4] = { h4.x, h4.y, h4.z, h4.w };
            uint32_t al[4] = { l4.x, l4.y, l4.z, l4.w };
#pragma unroll
            for (int i = 0; i < 13; i++) {
                int nt = nt0 + i;
                uint2 bh2 = *reinterpret_cast<const uint2*>(&smu[FKB_H + ((kc*26 + nt)*32 + lane)*2]);
                uint32_t bhv[2] = { bh2.x, bh2.y };
                mma_f16(acc[i], al, bhv);
                mma_f16(acc[i], ah, bhv);
            }
        }

        {
            float* ab = attn + (size_t)bh * N_ * N_;
            int r0 = qt * 64 + m * 16 + (lane >> 2);
            int cb = (lane & 3) * 2;
#pragma unroll
            for (int i = 0; i < 13; i++) {
                int col0 = (nt0 + i) * 8 + cb;
                if (r0 < N_) {
                    if (col0 < N_)     ab[(size_t)r0 * N_ + col0]     = acc[i][0];
                    if (col0 + 1 < N_) ab[(size_t)r0 * N_ + col0 + 1] = acc[i][1];
                }
                if (r0 + 8 < N_) {
                    if (col0 < N_)     ab[(size_t)(r0+8) * N_ + col0]     = acc[i][2];
                    if (col0 + 1 < N_) ab[(size_t)(r0+8) * N_ + col0 + 1] = acc[i][3];
                }
            }
        }

        float mx0 = -1e30f, mx1 = -1e30f;
#pragma unroll
        for (int i = 0; i < 13; i++) {
            int col0 = (nt0 + i) * 8 + (lane & 3) * 2;
            float2 mk = *reinterpret_cast<const float2*>(&msk[col0]);
            acc[i][0] += mk.x; acc[i][1] += mk.y;
            acc[i][2] += mk.x; acc[i][3] += mk.y;
            mx0 = fmaxf(mx0, fmaxf(acc[i][0], acc[i][1]));
            mx1 = fmaxf(mx1, fmaxf(acc[i][2], acc[i][3]));
        }
#pragma unroll
        for (int o = 1; o < 4; o <<= 1) {
            mx0 = fmaxf(mx0, __shfl_xor_sync(0xffffffffu, mx0, o));
            mx1 = fmaxf(mx1, __shfl_xor_sync(0xffffffffu, mx1, o));
        }
        if ((lane & 3) == 0) {
            rmax[half * 64 + m * 16 + (lane >> 2)]     = mx0;
            rmax[half * 64 + m * 16 + (lane >> 2) + 8] = mx1;
        }
    }
    __syncthreads();

    if (mvalid) {
        float mx0, mx1;
        {
            int rl = m * 16 + (lane >> 2);
            mx0 = fmaxf(rmax[rl], rmax[64 + rl]);
            mx1 = fmaxf(rmax[rl + 8], rmax[64 + rl + 8]);
        }
        float sum0 = 0.f, sum1 = 0.f;
#pragma unroll
        for (int i = 0; i < 13; i++) {
            pa0[i] = ex2_f16x2((acc[i][0] - mx0) * LOG2E_, (acc[i][1] - mx0) * LOG2E_);
            pa1[i] = ex2_f16x2((acc[i][2] - mx1) * LOG2E_, (acc[i][3] - mx1) * LOG2E_);
            float2 f0 = __half22float2(*reinterpret_cast<__half2*>(&pa0[i]));
            float2 f1 = __half22float2(*reinterpret_cast<__half2*>(&pa1[i]));
            sum0 += f0.x + f0.y;
            sum1 += f1.x + f1.y;
        }
#pragma unroll
        for (int o = 1; o < 4; o <<= 1) {
            sum0 += __shfl_xor_sync(0xffffffffu, sum0, o);
            sum1 += __shfl_xor_sync(0xffffffffu, sum1, o);
        }
        if ((lane & 3) == 0) {
            rsum[half * 64 + m * 16 + (lane >> 2)]     = sum0;
            rsum[half * 64 + m * 16 + (lane >> 2) + 8] = sum1;
        }
    }
    __syncthreads();

    if (mvalid) {
#pragma unroll
        for (int i = 0; i < 13; i++) {
            int nt = nt0 + i;
            int kcp = nt >> 1;
            int odd = nt & 1;
            int base = FPA + ((kcp*4 + m)*32 + lane)*4 + odd*2;
            smu[base]     = pa0[i];
            smu[base + 1] = pa1[i];
        }
    }
    __syncthreads();

    // ---- phase 2: ctx = P @ V (V single fp16), store fp16 ----
    const int mo = wid & 3;
    const int nq = wid >> 2;
    const bool movalid = (qt * 64 + mo * 16) < N_;

    if (movalid) {
        float acc2[4][4];
#pragma unroll
        for (int o = 0; o < 4; o++)
#pragma unroll
            for (int r = 0; r < 4; r++) acc2[o][r] = 0.f;

#pragma unroll
        for (int kcp = 0; kcp < 13; kcp++) {
            uint4 a4 = *reinterpret_cast<const uint4*>(&smu[FPA + ((kcp*4 + mo)*32 + lane)*4]);
            uint32_t av[4] = { a4.x, a4.y, a4.z, a4.w };
#pragma unroll
            for (int o = 0; o < 4; o++) {
                int ont = nq * 4 + o;
                uint2 bh2 = *reinterpret_cast<const uint2*>(&smu[FVB_H + ((kcp*8 + ont)*32 + lane)*2]);
                uint32_t bhv[2] = { bh2.x, bh2.y };
                mma_f16(acc2[o], av, bhv);
            }
        }

        int rl0 = mo * 16 + (lane >> 2);
        int row0 = qt * 64 + rl0;
        float inv0 = 1.f / (rsum[rl0] + rsum[64 + rl0]);
        float inv1 = 1.f / (rsum[rl0 + 8] + rsum[64 + rl0 + 8]);
#pragma unroll
        for (int o = 0; o < 4; o++) {
            int col0 = (nq * 4 + o) * 8 + (lane & 3) * 2;
            if (row0 < N_) {
                size_t off = ((size_t)(b * N_ + row0) * H_ + h) * HD_ + col0;
                __half2 hc = __floats2half2_rn(acc2[o][0] * inv0, acc2[o][1] * inv0);
                *reinterpret_cast<__half2*>(g_ctx + off) = hc;
            }
            if (row0 + 8 < N_) {
                size_t off = ((size_t)(b * N_ + row0 + 8) * H_ + h) * HD_ + col0;
                __half2 hc = __floats2half2_rn(acc2[o][2] * inv1, acc2[o][3] * inv1);
                *reinterpret_cast<__half2*>(g_ctx + off) = hc;
            }
        }
    }
}

// ---------------- launch ----------------
extern "C" void kernel_launch(void* const* d_in, const int* in_sizes, int n_in,
                              void* d_out, int out_size)
{
    const float* x      = (const float*)d_in[0];
    const float* qkv_w  = (const float*)d_in[1];
    const float* qkv_b  = (const float*)d_in[2];
    const float* proj_w = (const float*)d_in[3];
    const float* proj_b = (const float*)d_in[4];
    const int*   nkeep  = (const int*)  d_in[5];

    float* out       = (float*)d_out;                       // [B,N,C]
    float* keep_mask = out + (size_t)MROWS * C_;            // [B,N,1]
    float* attn      = keep_mask + MROWS;                   // [B,H,N,N]

    cudaFuncSetAttribute((const void*)gemm_mma<0>,
                         cudaFuncAttributeMaxDynamicSharedMemorySize, GEMM_SMEM_BYTES);
    cudaFuncSetAttribute((const void*)gemm_mma<1>,
                         cudaFuncAttributeMaxDynamicSharedMemorySize, GEMM_SMEM_BYTES);
    cudaFuncSetAttribute((const void*)fused_attn,
                         cudaFuncAttributeMaxDynamicSharedMemorySize, FUSED_SMEM_BYTES);

    // 0) proj_w fp32 -> fp16 (identical rn rounding to the old in-loader cvt)
    {
        int n4 = (C_ * C_) / 4;
        conv_w16<<<(n4 + 255) / 256, 256>>>(proj_w, n4);
    }

    // 1) qkv GEMM -> g_q (scaled), g_k, g_v  (v blocks 2-term)
    gemm_mma<0><<<dim3((3 * C_) / 128, (MROWS + 127) / 128), 256, GEMM_SMEM_BYTES>>>(
        x, qkv_w, qkv_b, nullptr, MROWS, 3 * C_, C_);

    // 2) cls scores + top-k -> g_mask, keep_mask (fp32, independent of fused S)
    cls_topk<<<B_, 256>>>(keep_mask, nkeep);

    // 3) fused scores + attn_rt write + softmax + AV -> g_ctx (fp16)
    fused_attn<<<dim3(4, BH_), 256, FUSED_SMEM_BYTES>>>(attn);

    // 4) proj GEMM -> out  (A fp16, B fp16, 1-term, pure-copy loader)
    gemm_mma<1><<<dim3(C_ / 128, (MROWS + 127) / 128), 256, GEMM_SMEM_BYTES>>>(
        nullptr, proj_w, proj_b, out, MROWS, C_, C_);
}